// round 15
// baseline (speedup 1.0000x reference)
#include <cuda_runtime.h>
#include <cuda_fp16.h>

// Problem constants
#define Bv 4
#define Sv 2048
#define Dv 1024
#define Hv 16
#define HDv 64
#define N3v 3072
#define Mv (Bv*Sv)   // 8192

// =============================================================================
// All MMA operands live in gmem as SW128-swizzled SMEM-image tiles:
// tile = 128 rows x 64 fp16 (128B rows, 16KB; attention tiles 64x64, 8KB).
// byte offset within tile: sw128(row*128 + kelem*2). cp.async is linear;
// fragment loads are ldmatrix.x4.
// =============================================================================

// ---------------- scratch (device globals; no runtime allocation) -------------
__device__ __align__(256) unsigned g_q [(size_t)Bv*Hv*Sv*32];    // fp16x2 rows, *0.125*log2e
__device__ __align__(256) unsigned g_k [(size_t)Bv*Hv*Sv*32];    // fp16x2 rows
__device__ __align__(256) unsigned g_v [(size_t)Bv*Hv*Sv*32];    // fp16x2 rows
__device__ __align__(256) unsigned g_ki[(size_t)Bv*Hv*32*2048];  // K tile images [key][hd]
__device__ __align__(256) unsigned g_vi[(size_t)Bv*Hv*32*2048];  // V^T tile images [hd][key]
__device__ __align__(256) int      g_kidx[Bv*Sv];
__device__ __align__(256) int      g_cnt[Bv];
// GEMM tile images: [tile128][chunk64k] -> 4096 words each
__device__ __align__(256) unsigned g_xa [(size_t)64*16*4096];
__device__ __align__(256) unsigned g_wi [(size_t)24*16*4096];
__device__ __align__(256) unsigned g_wo [(size_t)8*16*4096];
__device__ __align__(256) unsigned g_ci [(size_t)64*16*4096];

// ---------------- helpers -----------------------------------------------------
__device__ __forceinline__ unsigned pk2(float a, float b) {
    __half2 h = __floats2half2_rn(a, b);
    return *(unsigned*)&h;
}
__device__ __forceinline__ float ex2(float x) {
    float y;
    asm("ex2.approx.f32 %0, %1;" : "=f"(y) : "f"(x));
    return y;
}
__device__ __forceinline__ unsigned sw128(unsigned off) {
    return off ^ ((off >> 3) & 0x70);
}
__device__ __forceinline__ void mma16(float* c, const unsigned* a, const unsigned* b) {
    asm volatile(
        "mma.sync.aligned.m16n8k16.row.col.f32.f16.f16.f32 "
        "{%0,%1,%2,%3},{%4,%5,%6,%7},{%8,%9},{%0,%1,%2,%3};\n"
        : "+f"(c[0]), "+f"(c[1]), "+f"(c[2]), "+f"(c[3])
        : "r"(a[0]), "r"(a[1]), "r"(a[2]), "r"(a[3]),
          "r"(b[0]), "r"(b[1]));
}
__device__ __forceinline__ void ldsm4(unsigned* r, unsigned a) {
    asm volatile("ldmatrix.sync.aligned.m8n8.x4.shared.b16 {%0,%1,%2,%3}, [%4];"
                 : "=r"(r[0]), "=r"(r[1]), "=r"(r[2]), "=r"(r[3]) : "r"(a));
}
__device__ __forceinline__ void cpa16(unsigned sa, const void* g) {
    asm volatile("cp.async.cg.shared.global [%0], [%1], 16;\n" :: "r"(sa), "l"(g));
}
__device__ __forceinline__ void cpa_commit() {
    asm volatile("cp.async.commit_group;\n");
}
template<int N> __device__ __forceinline__ void cpa_wait() {
    asm volatile("cp.async.wait_group %0;\n" :: "n"(N));
}

// =============================================================================
// Mask scan: per batch, compacted key index list + count.
// =============================================================================
__global__ __launch_bounds__(256) void mask_scan(const int* __restrict__ mask)
{
    __shared__ int part[256];
    const int b = blockIdx.x, t = threadIdx.x;
    int loc[8], c = 0;
    #pragma unroll
    for (int j = 0; j < 8; j++) {
        loc[j] = mask[b * Sv + t * 8 + j] > 0;
        c += loc[j];
    }
    part[t] = c;
    __syncthreads();
    int pre = 0;
    for (int i = 0; i < t; i++) pre += part[i];
    int p = pre;
    #pragma unroll
    for (int j = 0; j < 8; j++)
        if (loc[j]) g_kidx[b * Sv + (p++)] = t * 8 + j;
    if (t == 255) g_cnt[b] = pre + c;
}

// =============================================================================
// Compact K/V into swizzled tile images. K: [key][hd]. V^T: [hd][key].
// grid (32, Hv, Bv), 256 threads.
// =============================================================================
__global__ __launch_bounds__(256) void compact_kv()
{
    __shared__ int sidx[64];
    __shared__ unsigned st[64][33];
    const int kt = blockIdx.x, h = blockIdx.y, b = blockIdx.z;
    const int cnt = g_cnt[b];
    if (kt * 64 >= cnt) return;
    const int bh = b * Hv + h;
    const int t = threadIdx.x;

    if (t < 64) {
        const int ci = kt * 64 + t;
        sidx[t] = (ci < cnt) ? g_kidx[b * Sv + ci] : -1;
    }
    __syncthreads();

    unsigned* kd = g_ki + ((size_t)(bh * 32 + kt)) * 2048;
    #pragma unroll
    for (int i = 0; i < 8; i++) {
        const int w = t + 256 * i;
        const int key = w >> 5, wk = w & 31;
        const int si = sidx[key];
        unsigned val = (si >= 0) ? g_k[((size_t)bh * Sv + si) * 32 + wk] : 0u;
        kd[sw128(key * 128 + wk * 4) >> 2] = val;
    }
    #pragma unroll
    for (int i = 0; i < 8; i++) {
        const int w = t + 256 * i;
        const int key = w >> 5, wk = w & 31;
        const int si = sidx[key];
        st[key][wk] = (si >= 0) ? g_v[((size_t)bh * Sv + si) * 32 + wk] : 0u;
    }
    __syncthreads();
    unsigned* vd = g_vi + ((size_t)(bh * 32 + kt)) * 2048;
    #pragma unroll
    for (int i = 0; i < 8; i++) {
        const int w = t + 256 * i;
        const int hd = w >> 5, kw = w & 31;
        unsigned sa = st[2 * kw][hd >> 1];
        unsigned sb = st[2 * kw + 1][hd >> 1];
        unsigned val = __byte_perm(sa, sb, (hd & 1) ? 0x7632 : 0x5410);
        vd[sw128(hd * 128 + kw * 4) >> 2] = val;
    }
}

// =============================================================================
// Prepass: pack X and W into swizzled fp16 tile images.
// =============================================================================
__global__ __launch_bounds__(256) void pack_x(const float* __restrict__ X)
{
    const int mtile = blockIdx.x, kb = blockIdx.y;
    const int t = threadIdx.x;
    const float* src = X + (size_t)(mtile * 128) * Dv + kb * 64;
    unsigned* dst = g_xa + ((size_t)(mtile * 16 + kb)) * 4096;
    #pragma unroll
    for (int i = 0; i < 16; i++) {
        const int w = t + 256 * i;
        const int row = w >> 5, wk = w & 31;
        float2 v = *(const float2*)(src + (size_t)row * Dv + 2 * wk);
        dst[sw128(row * 128 + wk * 4) >> 2] = pk2(v.x, v.y);
    }
}

template<int LDN>
__global__ __launch_bounds__(256) void pack_w(const float* __restrict__ W,
                                              unsigned* __restrict__ dstg)
{
    __shared__ float sb[64][129];
    const int ntile = blockIdx.x, kb = blockIdx.y;
    const int t = threadIdx.x;
    #pragma unroll
    for (int i = 0; i < 32; i++) {
        const int e = t + 256 * i;
        const int kk = e >> 7, nn = e & 127;
        sb[kk][nn] = W[(size_t)(kb * 64 + kk) * LDN + ntile * 128 + nn];
    }
    __syncthreads();
    unsigned* dst = dstg + ((size_t)(ntile * 16 + kb)) * 4096;
    #pragma unroll
    for (int i = 0; i < 16; i++) {
        const int w = t + 256 * i;
        const int nrow = w >> 5, wk = w & 31;
        dst[sw128(nrow * 128 + wk * 4) >> 2] = pk2(sb[2 * wk][nrow], sb[2 * wk + 1][nrow]);
    }
}

// =============================================================================
// QKV pair-store epilogue helper (n even; halves (n, n+1))
// =============================================================================
__device__ __forceinline__ void qkv_store2(int m, int n, float v0, float v1,
                                           const float* __restrict__ bias) {
    v0 += bias[n]; v1 += bias[n + 1];
    const int bb  = m >> 11;
    const int s   = m & 2047;
    const int sel = n >> 10;      // 0=q 1=k 2=v
    const int d   = n & 1023;
    const int h   = d >> 6;
    const int hw  = (d & 63) >> 1;
    const int bh  = bb * Hv + h;
    if (sel == 0) {
        const float qs = 0.18033688011112042f;   // 0.125*log2e
        g_q[((size_t)(bh * Sv + s)) * 32 + hw] = pk2(v0 * qs, v1 * qs);
    } else if (sel == 1) {
        g_k[((size_t)(bh * Sv + s)) * 32 + hw] = pk2(v0, v1);
    } else {
        g_v[((size_t)(bh * Sv + s)) * 32 + hw] = pk2(v0, v1);
    }
}

// =============================================================================
// fp16 GEMM on swizzled tile images. 128x128 CTA tile, BK=64, 8 warps,
// warp tile 32x64. 3-stage cp.async. ldmatrix.x4 fragments. 2 CTAs/SM.
// =============================================================================
#define GST 32768                    // stage bytes: A 16KB + B 16KB
#define GEMM_SMEM (3 * GST)

template<int NT, int EPI>
__global__ __launch_bounds__(256, 2) void gemm_tc(
    const unsigned* __restrict__ Ag,
    const unsigned* __restrict__ Bg,
    const float* __restrict__ bias,
    float* __restrict__ out)
{
    extern __shared__ unsigned char smem[];
    const unsigned sbase = (unsigned)__cvta_generic_to_shared(smem);

    const int t     = threadIdx.x;
    const int w     = t >> 5, lane = t & 31;
    const int g     = lane >> 2, tig = lane & 3;
    const int qd    = lane >> 3, r = lane & 7;
    const int ntile = blockIdx.x;
    const int mtile = blockIdx.y;
    const int m0w   = (w & 3) * 32;
    const int n0w   = (w >> 2) * 64;

    // ldmatrix per-lane address components
    const unsigned axor = r << 4;
    const unsigned aoff = (m0w + (qd & 1) * 8 + r) * 128;
    const unsigned akx  = (qd >> 1) * 16;
    const unsigned boff = (n0w + (qd >> 1) * 8 + r) * 128;
    const unsigned bkx  = (qd & 1) * 16;

    auto issue = [&](int st, int kb) {
        const char* asrc = (const char*)(Ag + ((size_t)(mtile * 16 + kb)) * 4096);
        const char* bsrc = (const char*)(Bg + ((size_t)(ntile * 16 + kb)) * 4096);
        #pragma unroll
        for (int i = 0; i < 4; i++) {
            const int e = (t + 256 * i) * 16;
            cpa16(sbase + st * GST + e, asrc + e);
            cpa16(sbase + st * GST + 16384 + e, bsrc + e);
        }
        cpa_commit();
    };

    float c[2][8][4];
    #pragma unroll
    for (int mt = 0; mt < 2; mt++)
        #pragma unroll
        for (int nt = 0; nt < 8; nt++)
            #pragma unroll
            for (int j = 0; j < 4; j++) c[mt][nt][j] = 0.f;

    issue(0, 0); issue(1, 1); issue(2, 2);

    int s = 0;
    for (int kb = 0; kb < 16; kb++) {
        cpa_wait<2>();
        __syncthreads();

        const unsigned Ab = sbase + s * GST;
        const unsigned Bb = Ab + 16384;

        #pragma unroll
        for (int ks = 0; ks < 4; ks++) {
            const unsigned ak = (ks * 32 + akx) ^ axor;
            const unsigned bk = (ks * 32 + bkx) ^ axor;
            unsigned af[2][4];
            ldsm4(af[0], Ab + aoff + ak);
            ldsm4(af[1], Ab + aoff + 2048 + ak);
            #pragma unroll
            for (int p = 0; p < 4; p++) {
                unsigned bf[4];
                ldsm4(bf, Bb + boff + p * 2048 + bk);
                mma16(c[0][2 * p],     af[0], bf);
                mma16(c[1][2 * p],     af[1], bf);
                mma16(c[0][2 * p + 1], af[0], bf + 2);
                mma16(c[1][2 * p + 1], af[1], bf + 2);
            }
        }
        __syncthreads();
        if (kb + 3 < 16) issue(s, kb + 3); else cpa_commit();
        s = (s == 2) ? 0 : s + 1;
    }

    const int row0 = mtile * 128, col0 = ntile * 128;
    if (EPI == 0) {
        #pragma unroll
        for (int mt = 0; mt < 2; mt++) {
            const int r0 = row0 + m0w + mt * 16 + g;
            const int r1 = r0 + 8;
            #pragma unroll
            for (int nt = 0; nt < 8; nt++) {
                const int n = col0 + n0w + nt * 8 + 2 * tig;
                qkv_store2(r0, n, c[mt][nt][0], c[mt][nt][1], bias);
                qkv_store2(r1, n, c[mt][nt][2], c[mt][nt][3], bias);
            }
        }
    } else {
        #pragma unroll
        for (int mt = 0; mt < 2; mt++) {
            const int r0 = row0 + m0w + mt * 16 + g;
            const int r1 = r0 + 8;
            #pragma unroll
            for (int nt = 0; nt < 8; nt++) {
                const int n = col0 + n0w + nt * 8 + 2 * tig;
                *(float2*)(out + (size_t)r0 * Dv + n) =
                    make_float2(c[mt][nt][0] + bias[n], c[mt][nt][1] + bias[n + 1]);
                *(float2*)(out + (size_t)r1 * Dv + n) =
                    make_float2(c[mt][nt][2] + bias[n], c[mt][nt][3] + bias[n + 1]);
            }
        }
    }
}

// =============================================================================
// fp16 flash attention over compacted swizzled K / V^T tile images.
// cp.async 2-stage, q-tile 128, 8 warps, log2 softmax, ldmatrix fragments.
// =============================================================================
#define AST3 16384                   // stage bytes: K 8KB + V 8KB
#define ATT_SMEM (2 * AST3)

__global__ __launch_bounds__(256, 2) void attn_tc()
{
    extern __shared__ unsigned char asmem[];
    const unsigned sbase = (unsigned)__cvta_generic_to_shared(asmem);

    const int t    = threadIdx.x;
    const int w    = t >> 5, lane = t & 31;
    const int g    = lane >> 2, tig = lane & 3;
    const int qd   = lane >> 3, r = lane & 7;
    const int qt   = blockIdx.x;
    const int h    = blockIdx.y;
    const int b    = blockIdx.z;
    const int bh   = b * Hv + h;

    const int cnt = g_cnt[b];
    const int nt_tiles = (cnt + 63) >> 6;

    // B-role ldmatrix address components (same for K and V^T tiles)
    const unsigned xorv = r << 4;
    const unsigned broff = ((qd >> 1) * 8 + r) * 128;
    const unsigned bkx   = (qd & 1) * 16;

    auto issue = [&](int st, int kt) {
        const char* ksrc = (const char*)(g_ki + ((size_t)(bh * 32 + kt)) * 2048);
        const char* vsrc = (const char*)(g_vi + ((size_t)(bh * 32 + kt)) * 2048);
        #pragma unroll
        for (int i = 0; i < 2; i++) {
            const int e = (t + 256 * i) * 16;
            cpa16(sbase + st * AST3 + e, ksrc + e);
            cpa16(sbase + st * AST3 + 8192 + e, vsrc + e);
        }
        cpa_commit();
    };

    // ---- preload Q fragments ----
    unsigned q[4][4];
    const unsigned* qp = g_q + ((size_t)bh * Sv + qt * 128 + w * 16) * 32;
    #pragma unroll
    for (int ks = 0; ks < 4; ks++) {
        q[ks][0] = qp[g * 32       + ks * 8 + tig];
        q[ks][1] = qp[(g + 8) * 32 + ks * 8 + tig];
        q[ks][2] = qp[g * 32       + ks * 8 + tig + 4];
        q[ks][3] = qp[(g + 8) * 32 + ks * 8 + tig + 4];
    }

    float o[8][4];
    #pragma unroll
    for (int nt = 0; nt < 8; nt++)
        #pragma unroll
        for (int j = 0; j < 4; j++) o[nt][j] = 0.f;

    float m0r = -1e30f, m1r = -1e30f, l0 = 0.f, l1 = 0.f;

    issue(0, 0);
    if (nt_tiles > 1) issue(1, 1); else cpa_commit();

    for (int kt = 0; kt < nt_tiles; kt++) {
        cpa_wait<1>();
        __syncthreads();

        const unsigned Kb = sbase + (kt & 1) * AST3;
        const unsigned Vb = Kb + 8192;

        // ---- S = Q K^T (log2 domain) ----
        float s[8][4];
        #pragma unroll
        for (int nt = 0; nt < 8; nt++)
            #pragma unroll
            for (int j = 0; j < 4; j++) s[nt][j] = 0.f;

        #pragma unroll
        for (int ks = 0; ks < 4; ks++) {
            const unsigned bk = (ks * 32 + bkx) ^ xorv;
            #pragma unroll
            for (int p = 0; p < 4; p++) {
                unsigned bf[4];
                ldsm4(bf, Kb + broff + p * 2048 + bk);
                mma16(s[2 * p],     q[ks], bf);
                mma16(s[2 * p + 1], q[ks], bf + 2);
            }
        }

        // ---- tail predicate (last tile only) ----
        const int limit = cnt - kt * 64;
        if (limit < 64) {
            #pragma unroll
            for (int nt = 0; nt < 8; nt++) {
                const int cc = nt * 8 + 2 * tig;
                if (cc >= limit)     { s[nt][0] = -1e30f; s[nt][2] = -1e30f; }
                if (cc + 1 >= limit) { s[nt][1] = -1e30f; s[nt][3] = -1e30f; }
            }
        }

        // ---- row max ----
        float mx0 = -1e30f, mx1 = -1e30f;
        #pragma unroll
        for (int nt = 0; nt < 8; nt++) {
            mx0 = fmaxf(mx0, fmaxf(s[nt][0], s[nt][1]));
            mx1 = fmaxf(mx1, fmaxf(s[nt][2], s[nt][3]));
        }
        mx0 = fmaxf(mx0, __shfl_xor_sync(0xffffffffu, mx0, 1));
        mx0 = fmaxf(mx0, __shfl_xor_sync(0xffffffffu, mx0, 2));
        mx1 = fmaxf(mx1, __shfl_xor_sync(0xffffffffu, mx1, 1));
        mx1 = fmaxf(mx1, __shfl_xor_sync(0xffffffffu, mx1, 2));

        const float mn0 = fmaxf(m0r, mx0);
        const float mn1 = fmaxf(m1r, mx1);
        const float cr0 = ex2(m0r - mn0);
        const float cr1 = ex2(m1r - mn1);
        m0r = mn0; m1r = mn1;

        // ---- exp2 + row sums ----
        float a0 = 0.f, a1 = 0.f;
        #pragma unroll
        for (int nt = 0; nt < 8; nt++) {
            s[nt][0] = ex2(s[nt][0] - mn0);
            s[nt][1] = ex2(s[nt][1] - mn0);
            s[nt][2] = ex2(s[nt][2] - mn1);
            s[nt][3] = ex2(s[nt][3] - mn1);
            a0 += s[nt][0] + s[nt][1];
            a1 += s[nt][2] + s[nt][3];
        }
        a0 += __shfl_xor_sync(0xffffffffu, a0, 1);
        a0 += __shfl_xor_sync(0xffffffffu, a0, 2);
        a1 += __shfl_xor_sync(0xffffffffu, a1, 1);
        a1 += __shfl_xor_sync(0xffffffffu, a1, 2);
        l0 = l0 * cr0 + a0;
        l1 = l1 * cr1 + a1;

        // ---- rescale O ----
        #pragma unroll
        for (int nt = 0; nt < 8; nt++) {
            o[nt][0] *= cr0; o[nt][1] *= cr0;
            o[nt][2] *= cr1; o[nt][3] *= cr1;
        }

        // ---- O += P V  (P packs straight into A-frags; B via ldmatrix) ----
        #pragma unroll
        for (int ks = 0; ks < 4; ks++) {
            unsigned a[4];
            a[0] = pk2(s[2*ks][0],     s[2*ks][1]);
            a[1] = pk2(s[2*ks][2],     s[2*ks][3]);
            a[2] = pk2(s[2*ks + 1][0], s[2*ks + 1][1]);
            a[3] = pk2(s[2*ks + 1][2], s[2*ks + 1][3]);
            const unsigned bk = (ks * 32 + bkx) ^ xorv;
            #pragma unroll
            for (int p = 0; p < 4; p++) {
                unsigned bf[4];
                ldsm4(bf, Vb + broff + p * 2048 + bk);
                mma16(o[2 * p],     a, bf);
                mma16(o[2 * p + 1], a, bf + 2);
            }
        }

        __syncthreads();
        if (kt + 2 < nt_tiles) issue(kt & 1, kt + 2); else cpa_commit();
    }

    // ---- normalize and write ctx tile image (swizzled) ----
    const float inv0 = 1.0f / l0;
    const float inv1 = 1.0f / l1;
    const int mtile = b * 16 + qt;
    const int tr = w * 16 + g;
    unsigned* cbase = g_ci + ((size_t)(mtile * 16 + h)) * 4096;
    #pragma unroll
    for (int nt = 0; nt < 8; nt++) {
        const int kin = nt * 8 + 2 * tig;
        cbase[sw128(tr * 128 + kin * 2) >> 2]       = pk2(o[nt][0] * inv0, o[nt][1] * inv0);
        cbase[sw128((tr + 8) * 128 + kin * 2) >> 2] = pk2(o[nt][2] * inv1, o[nt][3] * inv1);
    }
}

// =============================================================================
extern "C" void kernel_launch(void* const* d_in, const int* in_sizes, int n_in,
                              void* d_out, int out_size)
{
    const float* x     = (const float*)d_in[0];
    const float* w_in  = (const float*)d_in[1];
    const float* b_in  = (const float*)d_in[2];
    const float* w_out = (const float*)d_in[3];
    const float* b_out = (const float*)d_in[4];
    const int*   mask  = (const int*)d_in[5];
    float* out = (float*)d_out;

    cudaFuncSetAttribute(gemm_tc<24, 0>, cudaFuncAttributeMaxDynamicSharedMemorySize, GEMM_SMEM);
    cudaFuncSetAttribute(gemm_tc<8, 1>,  cudaFuncAttributeMaxDynamicSharedMemorySize, GEMM_SMEM);
    cudaFuncSetAttribute(attn_tc,        cudaFuncAttributeMaxDynamicSharedMemorySize, ATT_SMEM);

    unsigned *xa, *wi, *wo, *ci;
    cudaGetSymbolAddress((void**)&xa, g_xa);
    cudaGetSymbolAddress((void**)&wi, g_wi);
    cudaGetSymbolAddress((void**)&wo, g_wo);
    cudaGetSymbolAddress((void**)&ci, g_ci);

    mask_scan<<<Bv, 256>>>(mask);
    pack_x<<<dim3(64, 16), 256>>>(x);
    pack_w<N3v><<<dim3(24, 16), 256>>>(w_in, wi);
    pack_w<Dv><<<dim3(8, 16), 256>>>(w_out, wo);
    gemm_tc<24, 0><<<dim3(24, 64), 256, GEMM_SMEM>>>(xa, wi, b_in, nullptr);
    compact_kv<<<dim3(32, Hv, Bv), 256>>>();
    attn_tc<<<dim3(Sv / 128, Hv, Bv), 256, ATT_SMEM>>>();
    gemm_tc<8, 1><<<dim3(8, 64), 256, GEMM_SMEM>>>(ci, wo, b_out, out);
}

// round 16
// speedup vs baseline: 1.0002x; 1.0002x over previous
#include <cuda_runtime.h>
#include <cuda_fp16.h>

// Problem constants
#define Bv 4
#define Sv 2048
#define Dv 1024
#define Hv 16
#define HDv 64
#define N3v 3072
#define Mv (Bv*Sv)   // 8192

// =============================================================================
// All MMA operands live in gmem as SW128-swizzled SMEM-image tiles:
// tile = 128 rows x 64 fp16 (128B rows, 16KB; attention tiles 64x64, 8KB).
// byte offset within tile: sw128(row*128 + kelem*2). cp.async is linear;
// fragment loads are ldmatrix.x4.
// =============================================================================

// ---------------- scratch (device globals; no runtime allocation) -------------
__device__ __align__(256) unsigned g_q [(size_t)Bv*Hv*Sv*32];    // fp16x2 rows, *0.125*log2e
__device__ __align__(256) unsigned g_k [(size_t)Bv*Hv*Sv*32];    // fp16x2 rows
__device__ __align__(256) unsigned g_v [(size_t)Bv*Hv*Sv*32];    // fp16x2 rows
__device__ __align__(256) unsigned g_ki[(size_t)Bv*Hv*32*2048];  // K tile images [key][hd]
__device__ __align__(256) unsigned g_vi[(size_t)Bv*Hv*32*2048];  // V^T tile images [hd][key]
__device__ __align__(256) int      g_kidx[Bv*Sv];
__device__ __align__(256) int      g_cnt[Bv];
// GEMM tile images: [tile128][chunk64k] -> 4096 words each
__device__ __align__(256) unsigned g_xa [(size_t)64*16*4096];
__device__ __align__(256) unsigned g_wi [(size_t)24*16*4096];
__device__ __align__(256) unsigned g_wo [(size_t)8*16*4096];
__device__ __align__(256) unsigned g_ci [(size_t)64*16*4096];

// ---------------- helpers -----------------------------------------------------
__device__ __forceinline__ unsigned pk2(float a, float b) {
    __half2 h = __floats2half2_rn(a, b);
    return *(unsigned*)&h;
}
__device__ __forceinline__ float ex2(float x) {
    float y;
    asm("ex2.approx.f32 %0, %1;" : "=f"(y) : "f"(x));
    return y;
}
__device__ __forceinline__ unsigned sw128(unsigned off) {
    return off ^ ((off >> 3) & 0x70);
}
__device__ __forceinline__ void mma16(float* c, const unsigned* a, const unsigned* b) {
    asm volatile(
        "mma.sync.aligned.m16n8k16.row.col.f32.f16.f16.f32 "
        "{%0,%1,%2,%3},{%4,%5,%6,%7},{%8,%9},{%0,%1,%2,%3};\n"
        : "+f"(c[0]), "+f"(c[1]), "+f"(c[2]), "+f"(c[3])
        : "r"(a[0]), "r"(a[1]), "r"(a[2]), "r"(a[3]),
          "r"(b[0]), "r"(b[1]));
}
__device__ __forceinline__ void ldsm4(unsigned* r, unsigned a) {
    asm volatile("ldmatrix.sync.aligned.m8n8.x4.shared.b16 {%0,%1,%2,%3}, [%4];"
                 : "=r"(r[0]), "=r"(r[1]), "=r"(r[2]), "=r"(r[3]) : "r"(a));
}
__device__ __forceinline__ void cpa16(unsigned sa, const void* g) {
    asm volatile("cp.async.cg.shared.global [%0], [%1], 16;\n" :: "r"(sa), "l"(g));
}
__device__ __forceinline__ void cpa_commit() {
    asm volatile("cp.async.commit_group;\n");
}
template<int N> __device__ __forceinline__ void cpa_wait() {
    asm volatile("cp.async.wait_group %0;\n" :: "n"(N));
}

// =============================================================================
// Mask scan: per batch, compacted key index list + count.
// =============================================================================
__global__ __launch_bounds__(256) void mask_scan(const int* __restrict__ mask)
{
    __shared__ int part[256];
    const int b = blockIdx.x, t = threadIdx.x;
    int loc[8], c = 0;
    #pragma unroll
    for (int j = 0; j < 8; j++) {
        loc[j] = mask[b * Sv + t * 8 + j] > 0;
        c += loc[j];
    }
    part[t] = c;
    __syncthreads();
    int pre = 0;
    for (int i = 0; i < t; i++) pre += part[i];
    int p = pre;
    #pragma unroll
    for (int j = 0; j < 8; j++)
        if (loc[j]) g_kidx[b * Sv + (p++)] = t * 8 + j;
    if (t == 255) g_cnt[b] = pre + c;
}

// =============================================================================
// Compact K/V into swizzled tile images. K: [key][hd]. V^T: [hd][key].
// grid (32, Hv, Bv), 256 threads.
// =============================================================================
__global__ __launch_bounds__(256) void compact_kv()
{
    __shared__ int sidx[64];
    __shared__ unsigned st[64][33];
    const int kt = blockIdx.x, h = blockIdx.y, b = blockIdx.z;
    const int cnt = g_cnt[b];
    if (kt * 64 >= cnt) return;
    const int bh = b * Hv + h;
    const int t = threadIdx.x;

    if (t < 64) {
        const int ci = kt * 64 + t;
        sidx[t] = (ci < cnt) ? g_kidx[b * Sv + ci] : -1;
    }
    __syncthreads();

    unsigned* kd = g_ki + ((size_t)(bh * 32 + kt)) * 2048;
    #pragma unroll
    for (int i = 0; i < 8; i++) {
        const int w = t + 256 * i;
        const int key = w >> 5, wk = w & 31;
        const int si = sidx[key];
        unsigned val = (si >= 0) ? g_k[((size_t)bh * Sv + si) * 32 + wk] : 0u;
        kd[sw128(key * 128 + wk * 4) >> 2] = val;
    }
    #pragma unroll
    for (int i = 0; i < 8; i++) {
        const int w = t + 256 * i;
        const int key = w >> 5, wk = w & 31;
        const int si = sidx[key];
        st[key][wk] = (si >= 0) ? g_v[((size_t)bh * Sv + si) * 32 + wk] : 0u;
    }
    __syncthreads();
    unsigned* vd = g_vi + ((size_t)(bh * 32 + kt)) * 2048;
    #pragma unroll
    for (int i = 0; i < 8; i++) {
        const int w = t + 256 * i;
        const int hd = w >> 5, kw = w & 31;
        unsigned sa = st[2 * kw][hd >> 1];
        unsigned sb = st[2 * kw + 1][hd >> 1];
        unsigned val = __byte_perm(sa, sb, (hd & 1) ? 0x7632 : 0x5410);
        vd[sw128(hd * 128 + kw * 4) >> 2] = val;
    }
}

// =============================================================================
// Prepass: pack X and W into swizzled fp16 tile images.
// =============================================================================
__global__ __launch_bounds__(256) void pack_x(const float* __restrict__ X)
{
    const int mtile = blockIdx.x, kb = blockIdx.y;
    const int t = threadIdx.x;
    const float* src = X + (size_t)(mtile * 128) * Dv + kb * 64;
    unsigned* dst = g_xa + ((size_t)(mtile * 16 + kb)) * 4096;
    #pragma unroll
    for (int i = 0; i < 16; i++) {
        const int w = t + 256 * i;
        const int row = w >> 5, wk = w & 31;
        float2 v = *(const float2*)(src + (size_t)row * Dv + 2 * wk);
        dst[sw128(row * 128 + wk * 4) >> 2] = pk2(v.x, v.y);
    }
}

template<int LDN>
__global__ __launch_bounds__(256) void pack_w(const float* __restrict__ W,
                                              unsigned* __restrict__ dstg)
{
    __shared__ float sb[64][129];
    const int ntile = blockIdx.x, kb = blockIdx.y;
    const int t = threadIdx.x;
    #pragma unroll
    for (int i = 0; i < 32; i++) {
        const int e = t + 256 * i;
        const int kk = e >> 7, nn = e & 127;
        sb[kk][nn] = W[(size_t)(kb * 64 + kk) * LDN + ntile * 128 + nn];
    }
    __syncthreads();
    unsigned* dst = dstg + ((size_t)(ntile * 16 + kb)) * 4096;
    #pragma unroll
    for (int i = 0; i < 16; i++) {
        const int w = t + 256 * i;
        const int nrow = w >> 5, wk = w & 31;
        dst[sw128(nrow * 128 + wk * 4) >> 2] = pk2(sb[2 * wk][nrow], sb[2 * wk + 1][nrow]);
    }
}

// =============================================================================
// QKV pair-store epilogue helper (n even; halves (n, n+1))
// =============================================================================
__device__ __forceinline__ void qkv_store2(int m, int n, float v0, float v1,
                                           const float* __restrict__ bias) {
    v0 += bias[n]; v1 += bias[n + 1];
    const int bb  = m >> 11;
    const int s   = m & 2047;
    const int sel = n >> 10;      // 0=q 1=k 2=v
    const int d   = n & 1023;
    const int h   = d >> 6;
    const int hw  = (d & 63) >> 1;
    const int bh  = bb * Hv + h;
    if (sel == 0) {
        const float qs = 0.18033688011112042f;   // 0.125*log2e
        g_q[((size_t)(bh * Sv + s)) * 32 + hw] = pk2(v0 * qs, v1 * qs);
    } else if (sel == 1) {
        g_k[((size_t)(bh * Sv + s)) * 32 + hw] = pk2(v0, v1);
    } else {
        g_v[((size_t)(bh * Sv + s)) * 32 + hw] = pk2(v0, v1);
    }
}

// =============================================================================
// fp16 GEMM on swizzled tile images. 128x128 CTA tile, BK=64, 8 warps,
// warp tile 32x64. 3-stage cp.async. ldmatrix.x4 fragments. 2 CTAs/SM.
// =============================================================================
#define GST 32768                    // stage bytes: A 16KB + B 16KB
#define GEMM_SMEM (3 * GST)

template<int NT, int EPI>
__global__ __launch_bounds__(256, 2) void gemm_tc(
    const unsigned* __restrict__ Ag,
    const unsigned* __restrict__ Bg,
    const float* __restrict__ bias,
    float* __restrict__ out)
{
    extern __shared__ unsigned char smem[];
    const unsigned sbase = (unsigned)__cvta_generic_to_shared(smem);

    const int t     = threadIdx.x;
    const int w     = t >> 5, lane = t & 31;
    const int g     = lane >> 2, tig = lane & 3;
    const int qd    = lane >> 3, r = lane & 7;
    const int ntile = blockIdx.x;
    const int mtile = blockIdx.y;
    const int m0w   = (w & 3) * 32;
    const int n0w   = (w >> 2) * 64;

    // ldmatrix per-lane address components
    const unsigned axor = r << 4;
    const unsigned aoff = (m0w + (qd & 1) * 8 + r) * 128;
    const unsigned akx  = (qd >> 1) * 16;
    const unsigned boff = (n0w + (qd >> 1) * 8 + r) * 128;
    const unsigned bkx  = (qd & 1) * 16;

    auto issue = [&](int st, int kb) {
        const char* asrc = (const char*)(Ag + ((size_t)(mtile * 16 + kb)) * 4096);
        const char* bsrc = (const char*)(Bg + ((size_t)(ntile * 16 + kb)) * 4096);
        #pragma unroll
        for (int i = 0; i < 4; i++) {
            const int e = (t + 256 * i) * 16;
            cpa16(sbase + st * GST + e, asrc + e);
            cpa16(sbase + st * GST + 16384 + e, bsrc + e);
        }
        cpa_commit();
    };

    float c[2][8][4];
    #pragma unroll
    for (int mt = 0; mt < 2; mt++)
        #pragma unroll
        for (int nt = 0; nt < 8; nt++)
            #pragma unroll
            for (int j = 0; j < 4; j++) c[mt][nt][j] = 0.f;

    issue(0, 0); issue(1, 1); issue(2, 2);

    int s = 0;
    for (int kb = 0; kb < 16; kb++) {
        cpa_wait<2>();
        __syncthreads();

        const unsigned Ab = sbase + s * GST;
        const unsigned Bb = Ab + 16384;

        #pragma unroll
        for (int ks = 0; ks < 4; ks++) {
            const unsigned ak = (ks * 32 + akx) ^ axor;
            const unsigned bk = (ks * 32 + bkx) ^ axor;
            unsigned af[2][4];
            ldsm4(af[0], Ab + aoff + ak);
            ldsm4(af[1], Ab + aoff + 2048 + ak);
            #pragma unroll
            for (int p = 0; p < 4; p++) {
                unsigned bf[4];
                ldsm4(bf, Bb + boff + p * 2048 + bk);
                mma16(c[0][2 * p],     af[0], bf);
                mma16(c[1][2 * p],     af[1], bf);
                mma16(c[0][2 * p + 1], af[0], bf + 2);
                mma16(c[1][2 * p + 1], af[1], bf + 2);
            }
        }
        __syncthreads();
        if (kb + 3 < 16) issue(s, kb + 3); else cpa_commit();
        s = (s == 2) ? 0 : s + 1;
    }

    const int row0 = mtile * 128, col0 = ntile * 128;
    if (EPI == 0) {
        #pragma unroll
        for (int mt = 0; mt < 2; mt++) {
            const int r0 = row0 + m0w + mt * 16 + g;
            const int r1 = r0 + 8;
            #pragma unroll
            for (int nt = 0; nt < 8; nt++) {
                const int n = col0 + n0w + nt * 8 + 2 * tig;
                qkv_store2(r0, n, c[mt][nt][0], c[mt][nt][1], bias);
                qkv_store2(r1, n, c[mt][nt][2], c[mt][nt][3], bias);
            }
        }
    } else {
        #pragma unroll
        for (int mt = 0; mt < 2; mt++) {
            const int r0 = row0 + m0w + mt * 16 + g;
            const int r1 = r0 + 8;
            #pragma unroll
            for (int nt = 0; nt < 8; nt++) {
                const int n = col0 + n0w + nt * 8 + 2 * tig;
                *(float2*)(out + (size_t)r0 * Dv + n) =
                    make_float2(c[mt][nt][0] + bias[n], c[mt][nt][1] + bias[n + 1]);
                *(float2*)(out + (size_t)r1 * Dv + n) =
                    make_float2(c[mt][nt][2] + bias[n], c[mt][nt][3] + bias[n + 1]);
            }
        }
    }
}

// =============================================================================
// fp16 flash attention over compacted swizzled K / V^T tile images.
// cp.async 2-stage, q-tile 128, 8 warps, log2 softmax, ldmatrix fragments.
// =============================================================================
#define AST3 16384                   // stage bytes: K 8KB + V 8KB
#define ATT_SMEM (2 * AST3)

__global__ __launch_bounds__(256, 2) void attn_tc()
{
    extern __shared__ unsigned char asmem[];
    const unsigned sbase = (unsigned)__cvta_generic_to_shared(asmem);

    const int t    = threadIdx.x;
    const int w    = t >> 5, lane = t & 31;
    const int g    = lane >> 2, tig = lane & 3;
    const int qd   = lane >> 3, r = lane & 7;
    const int qt   = blockIdx.x;
    const int h    = blockIdx.y;
    const int b    = blockIdx.z;
    const int bh   = b * Hv + h;

    const int cnt = g_cnt[b];
    const int nt_tiles = (cnt + 63) >> 6;

    // B-role ldmatrix address components (same for K and V^T tiles)
    const unsigned xorv = r << 4;
    const unsigned broff = ((qd >> 1) * 8 + r) * 128;
    const unsigned bkx   = (qd & 1) * 16;

    auto issue = [&](int st, int kt) {
        const char* ksrc = (const char*)(g_ki + ((size_t)(bh * 32 + kt)) * 2048);
        const char* vsrc = (const char*)(g_vi + ((size_t)(bh * 32 + kt)) * 2048);
        #pragma unroll
        for (int i = 0; i < 2; i++) {
            const int e = (t + 256 * i) * 16;
            cpa16(sbase + st * AST3 + e, ksrc + e);
            cpa16(sbase + st * AST3 + 8192 + e, vsrc + e);
        }
        cpa_commit();
    };

    // ---- preload Q fragments ----
    unsigned q[4][4];
    const unsigned* qp = g_q + ((size_t)bh * Sv + qt * 128 + w * 16) * 32;
    #pragma unroll
    for (int ks = 0; ks < 4; ks++) {
        q[ks][0] = qp[g * 32       + ks * 8 + tig];
        q[ks][1] = qp[(g + 8) * 32 + ks * 8 + tig];
        q[ks][2] = qp[g * 32       + ks * 8 + tig + 4];
        q[ks][3] = qp[(g + 8) * 32 + ks * 8 + tig + 4];
    }

    float o[8][4];
    #pragma unroll
    for (int nt = 0; nt < 8; nt++)
        #pragma unroll
        for (int j = 0; j < 4; j++) o[nt][j] = 0.f;

    float m0r = -1e30f, m1r = -1e30f, l0 = 0.f, l1 = 0.f;

    issue(0, 0);
    if (nt_tiles > 1) issue(1, 1); else cpa_commit();

    for (int kt = 0; kt < nt_tiles; kt++) {
        cpa_wait<1>();
        __syncthreads();

        const unsigned Kb = sbase + (kt & 1) * AST3;
        const unsigned Vb = Kb + 8192;

        // ---- S = Q K^T (log2 domain) ----
        float s[8][4];
        #pragma unroll
        for (int nt = 0; nt < 8; nt++)
            #pragma unroll
            for (int j = 0; j < 4; j++) s[nt][j] = 0.f;

        #pragma unroll
        for (int ks = 0; ks < 4; ks++) {
            const unsigned bk = (ks * 32 + bkx) ^ xorv;
            #pragma unroll
            for (int p = 0; p < 4; p++) {
                unsigned bf[4];
                ldsm4(bf, Kb + broff + p * 2048 + bk);
                mma16(s[2 * p],     q[ks], bf);
                mma16(s[2 * p + 1], q[ks], bf + 2);
            }
        }

        // ---- tail predicate (last tile only) ----
        const int limit = cnt - kt * 64;
        if (limit < 64) {
            #pragma unroll
            for (int nt = 0; nt < 8; nt++) {
                const int cc = nt * 8 + 2 * tig;
                if (cc >= limit)     { s[nt][0] = -1e30f; s[nt][2] = -1e30f; }
                if (cc + 1 >= limit) { s[nt][1] = -1e30f; s[nt][3] = -1e30f; }
            }
        }

        // ---- row max ----
        float mx0 = -1e30f, mx1 = -1e30f;
        #pragma unroll
        for (int nt = 0; nt < 8; nt++) {
            mx0 = fmaxf(mx0, fmaxf(s[nt][0], s[nt][1]));
            mx1 = fmaxf(mx1, fmaxf(s[nt][2], s[nt][3]));
        }
        mx0 = fmaxf(mx0, __shfl_xor_sync(0xffffffffu, mx0, 1));
        mx0 = fmaxf(mx0, __shfl_xor_sync(0xffffffffu, mx0, 2));
        mx1 = fmaxf(mx1, __shfl_xor_sync(0xffffffffu, mx1, 1));
        mx1 = fmaxf(mx1, __shfl_xor_sync(0xffffffffu, mx1, 2));

        const float mn0 = fmaxf(m0r, mx0);
        const float mn1 = fmaxf(m1r, mx1);
        const float cr0 = ex2(m0r - mn0);
        const float cr1 = ex2(m1r - mn1);
        m0r = mn0; m1r = mn1;

        // ---- exp2 + row sums ----
        float a0 = 0.f, a1 = 0.f;
        #pragma unroll
        for (int nt = 0; nt < 8; nt++) {
            s[nt][0] = ex2(s[nt][0] - mn0);
            s[nt][1] = ex2(s[nt][1] - mn0);
            s[nt][2] = ex2(s[nt][2] - mn1);
            s[nt][3] = ex2(s[nt][3] - mn1);
            a0 += s[nt][0] + s[nt][1];
            a1 += s[nt][2] + s[nt][3];
        }
        a0 += __shfl_xor_sync(0xffffffffu, a0, 1);
        a0 += __shfl_xor_sync(0xffffffffu, a0, 2);
        a1 += __shfl_xor_sync(0xffffffffu, a1, 1);
        a1 += __shfl_xor_sync(0xffffffffu, a1, 2);
        l0 = l0 * cr0 + a0;
        l1 = l1 * cr1 + a1;

        // ---- rescale O ----
        #pragma unroll
        for (int nt = 0; nt < 8; nt++) {
            o[nt][0] *= cr0; o[nt][1] *= cr0;
            o[nt][2] *= cr1; o[nt][3] *= cr1;
        }

        // ---- O += P V  (P packs straight into A-frags; B via ldmatrix) ----
        #pragma unroll
        for (int ks = 0; ks < 4; ks++) {
            unsigned a[4];
            a[0] = pk2(s[2*ks][0],     s[2*ks][1]);
            a[1] = pk2(s[2*ks][2],     s[2*ks][3]);
            a[2] = pk2(s[2*ks + 1][0], s[2*ks + 1][1]);
            a[3] = pk2(s[2*ks + 1][2], s[2*ks + 1][3]);
            const unsigned bk = (ks * 32 + bkx) ^ xorv;
            #pragma unroll
            for (int p = 0; p < 4; p++) {
                unsigned bf[4];
                ldsm4(bf, Vb + broff + p * 2048 + bk);
                mma16(o[2 * p],     a, bf);
                mma16(o[2 * p + 1], a, bf + 2);
            }
        }

        __syncthreads();
        if (kt + 2 < nt_tiles) issue(kt & 1, kt + 2); else cpa_commit();
    }

    // ---- normalize and write ctx tile image (swizzled) ----
    const float inv0 = 1.0f / l0;
    const float inv1 = 1.0f / l1;
    const int mtile = b * 16 + qt;
    const int tr = w * 16 + g;
    unsigned* cbase = g_ci + ((size_t)(mtile * 16 + h)) * 4096;
    #pragma unroll
    for (int nt = 0; nt < 8; nt++) {
        const int kin = nt * 8 + 2 * tig;
        cbase[sw128(tr * 128 + kin * 2) >> 2]       = pk2(o[nt][0] * inv0, o[nt][1] * inv0);
        cbase[sw128((tr + 8) * 128 + kin * 2) >> 2] = pk2(o[nt][2] * inv1, o[nt][3] * inv1);
    }
}

// =============================================================================
extern "C" void kernel_launch(void* const* d_in, const int* in_sizes, int n_in,
                              void* d_out, int out_size)
{
    const float* x     = (const float*)d_in[0];
    const float* w_in  = (const float*)d_in[1];
    const float* b_in  = (const float*)d_in[2];
    const float* w_out = (const float*)d_in[3];
    const float* b_out = (const float*)d_in[4];
    const int*   mask  = (const int*)d_in[5];
    float* out = (float*)d_out;

    cudaFuncSetAttribute(gemm_tc<24, 0>, cudaFuncAttributeMaxDynamicSharedMemorySize, GEMM_SMEM);
    cudaFuncSetAttribute(gemm_tc<8, 1>,  cudaFuncAttributeMaxDynamicSharedMemorySize, GEMM_SMEM);
    cudaFuncSetAttribute(attn_tc,        cudaFuncAttributeMaxDynamicSharedMemorySize, ATT_SMEM);

    unsigned *xa, *wi, *wo, *ci;
    cudaGetSymbolAddress((void**)&xa, g_xa);
    cudaGetSymbolAddress((void**)&wi, g_wi);
    cudaGetSymbolAddress((void**)&wo, g_wo);
    cudaGetSymbolAddress((void**)&ci, g_ci);

    mask_scan<<<Bv, 256>>>(mask);
    pack_x<<<dim3(64, 16), 256>>>(x);
    pack_w<N3v><<<dim3(24, 16), 256>>>(w_in, wi);
    pack_w<Dv><<<dim3(8, 16), 256>>>(w_out, wo);
    gemm_tc<24, 0><<<dim3(24, 64), 256, GEMM_SMEM>>>(xa, wi, b_in, nullptr);
    compact_kv<<<dim3(32, Hv, Bv), 256>>>();
    attn_tc<<<dim3(Sv / 128, Hv, Bv), 256, ATT_SMEM>>>();
    gemm_tc<8, 1><<<dim3(8, 64), 256, GEMM_SMEM>>>(ci, wo, b_out, out);
}

// round 17
// speedup vs baseline: 1.0392x; 1.0390x over previous
#include <cuda_runtime.h>
#include <cuda_fp16.h>

// Problem constants
#define Bv 4
#define Sv 2048
#define Dv 1024
#define Hv 16
#define HDv 64
#define N3v 3072
#define Mv (Bv*Sv)   // 8192

// =============================================================================
// All MMA operands live in gmem as SW128-swizzled SMEM-image tiles:
// tile = 128 rows x 64 fp16 (128B rows, 16KB; attention tiles 64x64, 8KB).
// byte offset within tile: sw128(row*128 + kelem*2). cp.async is linear;
// fragment loads are ldmatrix.x4.
// =============================================================================

// ---------------- scratch (device globals; no runtime allocation) -------------
__device__ __align__(256) unsigned g_q [(size_t)Bv*Hv*Sv*32];    // fp16x2 rows, *0.125*log2e
__device__ __align__(256) unsigned g_k [(size_t)Bv*Hv*Sv*32];    // fp16x2 rows
__device__ __align__(256) unsigned g_v [(size_t)Bv*Hv*Sv*32];    // fp16x2 rows
__device__ __align__(256) unsigned g_ki[(size_t)Bv*Hv*32*2048];  // K tile images [key][hd]
__device__ __align__(256) unsigned g_vi[(size_t)Bv*Hv*32*2048];  // V^T tile images [hd][key]
__device__ __align__(256) int      g_kidx[Bv*Sv];
__device__ __align__(256) int      g_cnt[Bv];
// GEMM tile images: [tile128][chunk64k] -> 4096 words each
__device__ __align__(256) unsigned g_xa [(size_t)64*16*4096];
__device__ __align__(256) unsigned g_wi [(size_t)24*16*4096];
__device__ __align__(256) unsigned g_wo [(size_t)8*16*4096];
__device__ __align__(256) unsigned g_ci [(size_t)64*16*4096];

// ---------------- helpers -----------------------------------------------------
__device__ __forceinline__ unsigned pk2(float a, float b) {
    __half2 h = __floats2half2_rn(a, b);
    return *(unsigned*)&h;
}
__device__ __forceinline__ float ex2(float x) {
    float y;
    asm("ex2.approx.f32 %0, %1;" : "=f"(y) : "f"(x));
    return y;
}
__device__ __forceinline__ unsigned sw128(unsigned off) {
    return off ^ ((off >> 3) & 0x70);
}
__device__ __forceinline__ void mma16(float* c, const unsigned* a, const unsigned* b) {
    asm volatile(
        "mma.sync.aligned.m16n8k16.row.col.f32.f16.f16.f32 "
        "{%0,%1,%2,%3},{%4,%5,%6,%7},{%8,%9},{%0,%1,%2,%3};\n"
        : "+f"(c[0]), "+f"(c[1]), "+f"(c[2]), "+f"(c[3])
        : "r"(a[0]), "r"(a[1]), "r"(a[2]), "r"(a[3]),
          "r"(b[0]), "r"(b[1]));
}
__device__ __forceinline__ void ldsm4(unsigned* r, unsigned a) {
    asm volatile("ldmatrix.sync.aligned.m8n8.x4.shared.b16 {%0,%1,%2,%3}, [%4];"
                 : "=r"(r[0]), "=r"(r[1]), "=r"(r[2]), "=r"(r[3]) : "r"(a));
}
__device__ __forceinline__ void cpa16(unsigned sa, const void* g) {
    asm volatile("cp.async.cg.shared.global [%0], [%1], 16;\n" :: "r"(sa), "l"(g));
}
__device__ __forceinline__ void cpa_commit() {
    asm volatile("cp.async.commit_group;\n");
}
template<int N> __device__ __forceinline__ void cpa_wait() {
    asm volatile("cp.async.wait_group %0;\n" :: "n"(N));
}

// =============================================================================
// Mask scan: per batch, compacted key index list + count.
// =============================================================================
__global__ __launch_bounds__(256) void mask_scan(const int* __restrict__ mask)
{
    __shared__ int part[256];
    const int b = blockIdx.x, t = threadIdx.x;
    int loc[8], c = 0;
    #pragma unroll
    for (int j = 0; j < 8; j++) {
        loc[j] = mask[b * Sv + t * 8 + j] > 0;
        c += loc[j];
    }
    part[t] = c;
    __syncthreads();
    int pre = 0;
    for (int i = 0; i < t; i++) pre += part[i];
    int p = pre;
    #pragma unroll
    for (int j = 0; j < 8; j++)
        if (loc[j]) g_kidx[b * Sv + (p++)] = t * 8 + j;
    if (t == 255) g_cnt[b] = pre + c;
}

// =============================================================================
// Compact K/V into swizzled tile images. K: [key][hd]. V^T: [hd][key].
// grid (32, Hv, Bv), 256 threads.
// =============================================================================
__global__ __launch_bounds__(256) void compact_kv()
{
    __shared__ int sidx[64];
    __shared__ unsigned st[64][33];
    const int kt = blockIdx.x, h = blockIdx.y, b = blockIdx.z;
    const int cnt = g_cnt[b];
    if (kt * 64 >= cnt) return;
    const int bh = b * Hv + h;
    const int t = threadIdx.x;

    if (t < 64) {
        const int ci = kt * 64 + t;
        sidx[t] = (ci < cnt) ? g_kidx[b * Sv + ci] : -1;
    }
    __syncthreads();

    unsigned* kd = g_ki + ((size_t)(bh * 32 + kt)) * 2048;
    #pragma unroll
    for (int i = 0; i < 8; i++) {
        const int w = t + 256 * i;
        const int key = w >> 5, wk = w & 31;
        const int si = sidx[key];
        unsigned val = (si >= 0) ? g_k[((size_t)bh * Sv + si) * 32 + wk] : 0u;
        kd[sw128(key * 128 + wk * 4) >> 2] = val;
    }
    #pragma unroll
    for (int i = 0; i < 8; i++) {
        const int w = t + 256 * i;
        const int key = w >> 5, wk = w & 31;
        const int si = sidx[key];
        st[key][wk] = (si >= 0) ? g_v[((size_t)bh * Sv + si) * 32 + wk] : 0u;
    }
    __syncthreads();
    unsigned* vd = g_vi + ((size_t)(bh * 32 + kt)) * 2048;
    #pragma unroll
    for (int i = 0; i < 8; i++) {
        const int w = t + 256 * i;
        const int hd = w >> 5, kw = w & 31;
        unsigned sa = st[2 * kw][hd >> 1];
        unsigned sb = st[2 * kw + 1][hd >> 1];
        unsigned val = __byte_perm(sa, sb, (hd & 1) ? 0x7632 : 0x5410);
        vd[sw128(hd * 128 + kw * 4) >> 2] = val;
    }
}

// =============================================================================
// Prepass: pack X and W into swizzled fp16 tile images.
// =============================================================================
__global__ __launch_bounds__(256) void pack_x(const float* __restrict__ X)
{
    const int mtile = blockIdx.x, kb = blockIdx.y;
    const int t = threadIdx.x;
    const float* src = X + (size_t)(mtile * 128) * Dv + kb * 64;
    unsigned* dst = g_xa + ((size_t)(mtile * 16 + kb)) * 4096;
    #pragma unroll
    for (int i = 0; i < 16; i++) {
        const int w = t + 256 * i;
        const int row = w >> 5, wk = w & 31;
        float2 v = *(const float2*)(src + (size_t)row * Dv + 2 * wk);
        dst[sw128(row * 128 + wk * 4) >> 2] = pk2(v.x, v.y);
    }
}

// smem-free transposing pack: thread -> (nrow, wk); loads coalesced across n.
template<int LDN>
__global__ __launch_bounds__(256) void pack_w(const float* __restrict__ W,
                                              unsigned* __restrict__ dstg)
{
    const int ntile = blockIdx.x, kb = blockIdx.y;
    const int t = threadIdx.x;
    const float* src = W + (size_t)(kb * 64) * LDN + ntile * 128;
    unsigned* dst = dstg + ((size_t)(ntile * 16 + kb)) * 4096;
    #pragma unroll
    for (int i = 0; i < 16; i++) {
        const int w = t + 256 * i;
        const int wk = w >> 7, nrow = w & 127;     // wk slow: both loads hit
        const float* s0 = src + (size_t)(2 * wk) * LDN + nrow;
        float v0 = s0[0];
        float v1 = s0[LDN];
        dst[sw128(nrow * 128 + wk * 4) >> 2] = pk2(v0, v1);
    }
}

// =============================================================================
// QKV pair-store epilogue helper (n even; halves (n, n+1))
// =============================================================================
__device__ __forceinline__ void qkv_store2(int m, int n, float v0, float v1,
                                           const float* __restrict__ bias) {
    v0 += bias[n]; v1 += bias[n + 1];
    const int bb  = m >> 11;
    const int s   = m & 2047;
    const int sel = n >> 10;      // 0=q 1=k 2=v
    const int d   = n & 1023;
    const int h   = d >> 6;
    const int hw  = (d & 63) >> 1;
    const int bh  = bb * Hv + h;
    if (sel == 0) {
        const float qs = 0.18033688011112042f;   // 0.125*log2e
        g_q[((size_t)(bh * Sv + s)) * 32 + hw] = pk2(v0 * qs, v1 * qs);
    } else if (sel == 1) {
        g_k[((size_t)(bh * Sv + s)) * 32 + hw] = pk2(v0, v1);
    } else {
        g_v[((size_t)(bh * Sv + s)) * 32 + hw] = pk2(v0, v1);
    }
}

// =============================================================================
// fp16 GEMM on swizzled tile images. 128x128 CTA tile, BK=64, 8 warps,
// warp tile 32x64. 3-stage cp.async, SINGLE sync per k-iter. 2 CTAs/SM.
// =============================================================================
#define GST 32768                    // stage bytes: A 16KB + B 16KB
#define GEMM_SMEM (3 * GST)

template<int NT, int EPI>
__global__ __launch_bounds__(256, 2) void gemm_tc(
    const unsigned* __restrict__ Ag,
    const unsigned* __restrict__ Bg,
    const float* __restrict__ bias,
    float* __restrict__ out)
{
    extern __shared__ unsigned char smem[];
    const unsigned sbase = (unsigned)__cvta_generic_to_shared(smem);

    const int t     = threadIdx.x;
    const int w     = t >> 5, lane = t & 31;
    const int g     = lane >> 2, tig = lane & 3;
    const int qd    = lane >> 3, r = lane & 7;
    const int ntile = blockIdx.x;
    const int mtile = blockIdx.y;
    const int m0w   = (w & 3) * 32;
    const int n0w   = (w >> 2) * 64;

    // ldmatrix per-lane address components
    const unsigned axor = r << 4;
    const unsigned aoff = (m0w + (qd & 1) * 8 + r) * 128;
    const unsigned akx  = (qd >> 1) * 16;
    const unsigned boff = (n0w + (qd >> 1) * 8 + r) * 128;
    const unsigned bkx  = (qd & 1) * 16;

    auto issue = [&](int st, int kb) {
        const char* asrc = (const char*)(Ag + ((size_t)(mtile * 16 + kb)) * 4096);
        const char* bsrc = (const char*)(Bg + ((size_t)(ntile * 16 + kb)) * 4096);
        #pragma unroll
        for (int i = 0; i < 4; i++) {
            const int e = (t + 256 * i) * 16;
            cpa16(sbase + st * GST + e, asrc + e);
            cpa16(sbase + st * GST + 16384 + e, bsrc + e);
        }
        cpa_commit();
    };

    float c[2][8][4];
    #pragma unroll
    for (int mt = 0; mt < 2; mt++)
        #pragma unroll
        for (int nt = 0; nt < 8; nt++)
            #pragma unroll
            for (int j = 0; j < 4; j++) c[mt][nt][j] = 0.f;

    issue(0, 0); issue(1, 1);

    int s = 0, s2 = 2;                 // s = slot of kb, s2 = slot of kb+2
    for (int kb = 0; kb < 16; kb++) {
        cpa_wait<1>();
        __syncthreads();               // single barrier: kb ready AND slot s2 free
        if (kb + 2 < 16) issue(s2, kb + 2); else cpa_commit();

        const unsigned Ab = sbase + s * GST;
        const unsigned Bb = Ab + 16384;

        #pragma unroll
        for (int ks = 0; ks < 4; ks++) {
            const unsigned ak = (ks * 32 + akx) ^ axor;
            const unsigned bk = (ks * 32 + bkx) ^ axor;
            unsigned af[2][4];
            ldsm4(af[0], Ab + aoff + ak);
            ldsm4(af[1], Ab + aoff + 2048 + ak);
            #pragma unroll
            for (int p = 0; p < 4; p++) {
                unsigned bf[4];
                ldsm4(bf, Bb + boff + p * 2048 + bk);
                mma16(c[0][2 * p],     af[0], bf);
                mma16(c[1][2 * p],     af[1], bf);
                mma16(c[0][2 * p + 1], af[0], bf + 2);
                mma16(c[1][2 * p + 1], af[1], bf + 2);
            }
        }
        s  = (s  == 2) ? 0 : s  + 1;
        s2 = (s2 == 2) ? 0 : s2 + 1;
    }

    const int row0 = mtile * 128, col0 = ntile * 128;
    if (EPI == 0) {
        #pragma unroll
        for (int mt = 0; mt < 2; mt++) {
            const int r0 = row0 + m0w + mt * 16 + g;
            const int r1 = r0 + 8;
            #pragma unroll
            for (int nt = 0; nt < 8; nt++) {
                const int n = col0 + n0w + nt * 8 + 2 * tig;
                qkv_store2(r0, n, c[mt][nt][0], c[mt][nt][1], bias);
                qkv_store2(r1, n, c[mt][nt][2], c[mt][nt][3], bias);
            }
        }
    } else {
        #pragma unroll
        for (int mt = 0; mt < 2; mt++) {
            const int r0 = row0 + m0w + mt * 16 + g;
            const int r1 = r0 + 8;
            #pragma unroll
            for (int nt = 0; nt < 8; nt++) {
                const int n = col0 + n0w + nt * 8 + 2 * tig;
                *(float2*)(out + (size_t)r0 * Dv + n) =
                    make_float2(c[mt][nt][0] + bias[n], c[mt][nt][1] + bias[n + 1]);
                *(float2*)(out + (size_t)r1 * Dv + n) =
                    make_float2(c[mt][nt][2] + bias[n], c[mt][nt][3] + bias[n + 1]);
            }
        }
    }
}

// =============================================================================
// fp16 flash attention over compacted swizzled K / V^T tile images.
// 3-stage cp.async, single sync/iter, q-tile 128, 8 warps, log2 softmax.
// =============================================================================
#define AST3 16384                   // stage bytes: K 8KB + V 8KB
#define ATT_SMEM (3 * AST3)

__global__ __launch_bounds__(256, 2) void attn_tc()
{
    extern __shared__ unsigned char asmem[];
    const unsigned sbase = (unsigned)__cvta_generic_to_shared(asmem);

    const int t    = threadIdx.x;
    const int w    = t >> 5, lane = t & 31;
    const int g    = lane >> 2, tig = lane & 3;
    const int qd   = lane >> 3, r = lane & 7;
    const int qt   = blockIdx.x;
    const int h    = blockIdx.y;
    const int b    = blockIdx.z;
    const int bh   = b * Hv + h;

    const int cnt = g_cnt[b];
    const int nt_tiles = (cnt + 63) >> 6;

    // B-role ldmatrix address components (same for K and V^T tiles)
    const unsigned xorv = r << 4;
    const unsigned broff = ((qd >> 1) * 8 + r) * 128;
    const unsigned bkx   = (qd & 1) * 16;

    auto issue = [&](int st, int kt) {
        const char* ksrc = (const char*)(g_ki + ((size_t)(bh * 32 + kt)) * 2048);
        const char* vsrc = (const char*)(g_vi + ((size_t)(bh * 32 + kt)) * 2048);
        #pragma unroll
        for (int i = 0; i < 2; i++) {
            const int e = (t + 256 * i) * 16;
            cpa16(sbase + st * AST3 + e, ksrc + e);
            cpa16(sbase + st * AST3 + 8192 + e, vsrc + e);
        }
        cpa_commit();
    };

    // ---- preload Q fragments ----
    unsigned q[4][4];
    const unsigned* qp = g_q + ((size_t)bh * Sv + qt * 128 + w * 16) * 32;
    #pragma unroll
    for (int ks = 0; ks < 4; ks++) {
        q[ks][0] = qp[g * 32       + ks * 8 + tig];
        q[ks][1] = qp[(g + 8) * 32 + ks * 8 + tig];
        q[ks][2] = qp[g * 32       + ks * 8 + tig + 4];
        q[ks][3] = qp[(g + 8) * 32 + ks * 8 + tig + 4];
    }

    float o[8][4];
    #pragma unroll
    for (int nt = 0; nt < 8; nt++)
        #pragma unroll
        for (int j = 0; j < 4; j++) o[nt][j] = 0.f;

    float m0r = -1e30f, m1r = -1e30f, l0 = 0.f, l1 = 0.f;

    issue(0, 0);
    if (nt_tiles > 1) issue(1, 1); else cpa_commit();

    int s = 0, s2 = 2;
    for (int kt = 0; kt < nt_tiles; kt++) {
        cpa_wait<1>();
        __syncthreads();               // single barrier per tile
        if (kt + 2 < nt_tiles) issue(s2, kt + 2); else cpa_commit();

        const unsigned Kb = sbase + s * AST3;
        const unsigned Vb = Kb + 8192;

        // ---- S = Q K^T (log2 domain) ----
        float sc[8][4];
        #pragma unroll
        for (int nt = 0; nt < 8; nt++)
            #pragma unroll
            for (int j = 0; j < 4; j++) sc[nt][j] = 0.f;

        #pragma unroll
        for (int ks = 0; ks < 4; ks++) {
            const unsigned bk = (ks * 32 + bkx) ^ xorv;
            #pragma unroll
            for (int p = 0; p < 4; p++) {
                unsigned bf[4];
                ldsm4(bf, Kb + broff + p * 2048 + bk);
                mma16(sc[2 * p],     q[ks], bf);
                mma16(sc[2 * p + 1], q[ks], bf + 2);
            }
        }

        // ---- tail predicate (last tile only) ----
        const int limit = cnt - kt * 64;
        if (limit < 64) {
            #pragma unroll
            for (int nt = 0; nt < 8; nt++) {
                const int cc = nt * 8 + 2 * tig;
                if (cc >= limit)     { sc[nt][0] = -1e30f; sc[nt][2] = -1e30f; }
                if (cc + 1 >= limit) { sc[nt][1] = -1e30f; sc[nt][3] = -1e30f; }
            }
        }

        // ---- row max ----
        float mx0 = -1e30f, mx1 = -1e30f;
        #pragma unroll
        for (int nt = 0; nt < 8; nt++) {
            mx0 = fmaxf(mx0, fmaxf(sc[nt][0], sc[nt][1]));
            mx1 = fmaxf(mx1, fmaxf(sc[nt][2], sc[nt][3]));
        }
        mx0 = fmaxf(mx0, __shfl_xor_sync(0xffffffffu, mx0, 1));
        mx0 = fmaxf(mx0, __shfl_xor_sync(0xffffffffu, mx0, 2));
        mx1 = fmaxf(mx1, __shfl_xor_sync(0xffffffffu, mx1, 1));
        mx1 = fmaxf(mx1, __shfl_xor_sync(0xffffffffu, mx1, 2));

        const float mn0 = fmaxf(m0r, mx0);
        const float mn1 = fmaxf(m1r, mx1);
        const float cr0 = ex2(m0r - mn0);
        const float cr1 = ex2(m1r - mn1);
        m0r = mn0; m1r = mn1;

        // ---- exp2 + row sums ----
        float a0 = 0.f, a1 = 0.f;
        #pragma unroll
        for (int nt = 0; nt < 8; nt++) {
            sc[nt][0] = ex2(sc[nt][0] - mn0);
            sc[nt][1] = ex2(sc[nt][1] - mn0);
            sc[nt][2] = ex2(sc[nt][2] - mn1);
            sc[nt][3] = ex2(sc[nt][3] - mn1);
            a0 += sc[nt][0] + sc[nt][1];
            a1 += sc[nt][2] + sc[nt][3];
        }
        a0 += __shfl_xor_sync(0xffffffffu, a0, 1);
        a0 += __shfl_xor_sync(0xffffffffu, a0, 2);
        a1 += __shfl_xor_sync(0xffffffffu, a1, 1);
        a1 += __shfl_xor_sync(0xffffffffu, a1, 2);
        l0 = l0 * cr0 + a0;
        l1 = l1 * cr1 + a1;

        // ---- rescale O ----
        #pragma unroll
        for (int nt = 0; nt < 8; nt++) {
            o[nt][0] *= cr0; o[nt][1] *= cr0;
            o[nt][2] *= cr1; o[nt][3] *= cr1;
        }

        // ---- O += P V  (P packs straight into A-frags; B via ldmatrix) ----
        #pragma unroll
        for (int ks = 0; ks < 4; ks++) {
            unsigned a[4];
            a[0] = pk2(sc[2*ks][0],     sc[2*ks][1]);
            a[1] = pk2(sc[2*ks][2],     sc[2*ks][3]);
            a[2] = pk2(sc[2*ks + 1][0], sc[2*ks + 1][1]);
            a[3] = pk2(sc[2*ks + 1][2], sc[2*ks + 1][3]);
            const unsigned bk = (ks * 32 + bkx) ^ xorv;
            #pragma unroll
            for (int p = 0; p < 4; p++) {
                unsigned bf[4];
                ldsm4(bf, Vb + broff + p * 2048 + bk);
                mma16(o[2 * p],     a, bf);
                mma16(o[2 * p + 1], a, bf + 2);
            }
        }
        s  = (s  == 2) ? 0 : s  + 1;
        s2 = (s2 == 2) ? 0 : s2 + 1;
    }

    // ---- normalize and write ctx tile image (swizzled) ----
    const float inv0 = 1.0f / l0;
    const float inv1 = 1.0f / l1;
    const int mtile = b * 16 + qt;
    const int tr = w * 16 + g;
    unsigned* cbase = g_ci + ((size_t)(mtile * 16 + h)) * 4096;
    #pragma unroll
    for (int nt = 0; nt < 8; nt++) {
        const int kin = nt * 8 + 2 * tig;
        cbase[sw128(tr * 128 + kin * 2) >> 2]       = pk2(o[nt][0] * inv0, o[nt][1] * inv0);
        cbase[sw128((tr + 8) * 128 + kin * 2) >> 2] = pk2(o[nt][2] * inv1, o[nt][3] * inv1);
    }
}

// =============================================================================
extern "C" void kernel_launch(void* const* d_in, const int* in_sizes, int n_in,
                              void* d_out, int out_size)
{
    const float* x     = (const float*)d_in[0];
    const float* w_in  = (const float*)d_in[1];
    const float* b_in  = (const float*)d_in[2];
    const float* w_out = (const float*)d_in[3];
    const float* b_out = (const float*)d_in[4];
    const int*   mask  = (const int*)d_in[5];
    float* out = (float*)d_out;

    cudaFuncSetAttribute(gemm_tc<24, 0>, cudaFuncAttributeMaxDynamicSharedMemorySize, GEMM_SMEM);
    cudaFuncSetAttribute(gemm_tc<8, 1>,  cudaFuncAttributeMaxDynamicSharedMemorySize, GEMM_SMEM);
    cudaFuncSetAttribute(attn_tc,        cudaFuncAttributeMaxDynamicSharedMemorySize, ATT_SMEM);

    unsigned *xa, *wi, *wo, *ci;
    cudaGetSymbolAddress((void**)&xa, g_xa);
    cudaGetSymbolAddress((void**)&wi, g_wi);
    cudaGetSymbolAddress((void**)&wo, g_wo);
    cudaGetSymbolAddress((void**)&ci, g_ci);

    mask_scan<<<Bv, 256>>>(mask);
    pack_x<<<dim3(64, 16), 256>>>(x);
    pack_w<N3v><<<dim3(24, 16), 256>>>(w_in, wi);
    pack_w<Dv><<<dim3(8, 16), 256>>>(w_out, wo);
    gemm_tc<24, 0><<<dim3(24, 64), 256, GEMM_SMEM>>>(xa, wi, b_in, nullptr);
    compact_kv<<<dim3(32, Hv, Bv), 256>>>();
    attn_tc<<<dim3(Sv / 128, Hv, Bv), 256, ATT_SMEM>>>();
    gemm_tc<8, 1><<<dim3(8, 64), 256, GEMM_SMEM>>>(ci, wo, b_out, out);
}